// round 17
// baseline (speedup 1.0000x reference)
#include <cuda_runtime.h>
#include <cuda_bf16.h>

#define MODIFIER_COL 11
#define OWNER_COL    24
#define MAXG         8192
#define F_DIM        128
#define WAITER_BLOCKS  8
#define WAITER_THREADS (WAITER_BLOCKS * 256)

// Per-graph 16B slot {count, s0, s1, 0}: all contributions via ONE relaxed
// no-return v4 RED per segment head (same-address L2 serialization => when
// count==expected, all components are complete; snapshot untorn — validated
// in R15/R16). Boundary-position arrays: each entry has exactly one writer
// (the scan thread seeing that transition) and one reader (waiter g), so
// plain volatile stores/loads and single-reader resets are race-free.
// All zero-init; consumed entries reset by their unique reader each replay.
__device__ float4 g_state[MAXG];
__device__ int    g_senc[MAXG];    // start index + 1 (0 = unset)
__device__ int    g_eenc[MAXG];    // one-past-end index + 1 (0 = unset)

__device__ __forceinline__ void red_add_v4_relaxed(float4* p, float4 d)
{
    asm volatile("red.relaxed.gpu.global.add.v4.f32 [%0], {%1,%2,%3,%4};"
                 :: "l"(p), "f"(d.x), "f"(d.y), "f"(d.z), "f"(d.w) : "memory");
}
__device__ __forceinline__ float4 ldv_v4(const float4* p)
{
    float4 v;
    asm volatile("ld.volatile.global.v4.f32 {%0,%1,%2,%3}, [%4];"
                 : "=f"(v.x), "=f"(v.y), "=f"(v.z), "=f"(v.w) : "l"(p) : "memory");
    return v;
}
__device__ __forceinline__ void stv_v4(float4* p, float4 v)
{
    asm volatile("st.volatile.global.v4.f32 [%0], {%1,%2,%3,%4};"
                 :: "l"(p), "f"(v.x), "f"(v.y), "f"(v.z), "f"(v.w) : "memory");
}
__device__ __forceinline__ int  ldv_i32(const int* p)
{
    int v;
    asm volatile("ld.volatile.global.s32 %0, [%1];" : "=r"(v) : "l"(p) : "memory");
    return v;
}
__device__ __forceinline__ void stv_i32(int* p, int v)
{
    asm volatile("st.volatile.global.s32 [%0], %1;" :: "l"(p), "r"(v) : "memory");
}

// Boundary at position p: batch[p-1]=a, batch[p]=b, a!=b. enc = p+1.
__device__ __forceinline__ void mark_boundary(int a, int b, int enc, int G)
{
    stv_i32(g_eenc + a, enc);
    stv_i32(g_senc + b, enc);
    for (int h = a + 1; h < b && h < G; ++h) {      // empty graphs in the gap
        stv_i32(g_senc + h, enc);
        stv_i32(g_eenc + h, enc);
    }
}

__global__ __launch_bounds__(256) void fused_kernel(
    const float* __restrict__ nf,
    const int*   __restrict__ batch,
    const float* __restrict__ W1,   // [32,2] row-major
    const float* __restrict__ b1,   // [32]
    const float* __restrict__ W2,   // [1,32]
    const float* __restrict__ b2,   // [1]
    float* __restrict__ out,
    int N, int G)
{
    if (blockIdx.x < WAITER_BLOCKS) {
        // ============================ waiter block ============================
        __shared__ float sW1[64], sb1[32], sW2[32];
        __shared__ float sb2;
        const int t    = threadIdx.x;
        const int wtid = blockIdx.x * 256 + t;

        if (t < 64)        sW1[t]      = W1[t];       // cold fetch early
        else if (t < 96)   sb1[t - 64] = b1[t - 64];
        else if (t < 128)  sW2[t - 96] = W2[t - 96];
        if (t == 0)        sb2 = *b2;

        // ---- boundary scan: coalesced int4 stream over sorted keys ----
        const int  nvec = N >> 2;
        const int4* b4  = reinterpret_cast<const int4*>(batch);
        for (int v = wtid; v < nvec; v += WAITER_THREADS) {
            int4 k = __ldg(b4 + v);
            int base = v << 2;
            if (k.y != k.x) mark_boundary(k.x, k.y, base + 2, G);
            if (k.z != k.y) mark_boundary(k.y, k.z, base + 3, G);
            if (k.w != k.z) mark_boundary(k.z, k.w, base + 4, G);
            if (base + 4 < N) {
                int nxt = __ldg(batch + base + 4);
                if (nxt != k.w) mark_boundary(k.w, nxt, base + 5, G);
            } else {                                   // global end
                stv_i32(g_eenc + k.w, N + 1);
                for (int h = k.w + 1; h < G && h < MAXG; ++h) {
                    stv_i32(g_senc + h, N + 1);
                    stv_i32(g_eenc + h, N + 1);
                }
            }
            if (v == 0) {                              // global start
                stv_i32(g_senc + k.x, 1);
                for (int h = 0; h < k.x && h < MAXG; ++h) {
                    stv_i32(g_senc + h, 1);
                    stv_i32(g_eenc + h, 1);
                }
            }
        }
        for (int p = (nvec << 2) + (wtid ? wtid : WAITER_THREADS); p < N;
             p += WAITER_THREADS) {                    // scalar tail (N%4)
            int a = __ldg(batch + p - 1), b = __ldg(batch + p);
            if (b != a) mark_boundary(a, b, p + 1, G);
            if (p == N - 1) stv_i32(g_eenc + b, N + 1);
        }
        __syncthreads();

        // ---- wait + finalize: one graph per waiter thread ----
        int g = wtid;
        if (g >= G || g >= MAXG) return;

        int s, e;
        while ((s = ldv_i32(g_senc + g)) == 0) __nanosleep(200);
        while ((e = ldv_i32(g_eenc + g)) == 0) __nanosleep(200);
        stv_i32(g_senc + g, 0);                        // unique reader: safe
        stv_i32(g_eenc + g, 0);
        int cnt = e - s;

        if (cnt <= 0) { out[g] = 0.f; return; }        // empty graph

        float fc = (float)cnt;                         // < 2^24: exact
        float4 st;
        while (true) {
            st = ldv_v4(&g_state[g]);
            if (st.x == fc) break;                     // all heads landed
            __nanosleep(200);
        }
        stv_v4(&g_state[g], make_float4(0.f, 0.f, 0.f, 0.f));  // reset

        float f0 = 1.f - st.y / fc;
        float f1 = 1.f - st.z / fc;
        float acc = sb2;
        #pragma unroll
        for (int j = 0; j < 32; ++j) {
            float h = fmaf(f0, sW1[2 * j], fmaf(f1, sW1[2 * j + 1], sb1[j]));
            h   = fmaxf(h, 0.f);
            acc = fmaf(sW2[j], h, acc);
        }
        out[g] = 1.f / (1.f + __expf(-acc));
        return;
    }

    // ======================= reduce (R2 hot path + 1 RED) =======================
    const int i    = (blockIdx.x - WAITER_BLOCKS) * blockDim.x + threadIdx.x;
    const int lane = threadIdx.x & 31;

    int   g  = -1;
    float c  = 0.f, v0 = 0.f, v1 = 0.f;
    if (i < N) {
        g  = batch[i];
        const float* row = nf + (size_t)i * F_DIM;
        v0 = __ldg(row + MODIFIER_COL);
        v1 = __ldg(row + OWNER_COL);
        c  = 1.f;
    }

    #pragma unroll
    for (int d = 1; d < 32; d <<= 1) {
        int   go = __shfl_down_sync(0xffffffffu, g,  d);
        float co = __shfl_down_sync(0xffffffffu, c,  d);
        float a0 = __shfl_down_sync(0xffffffffu, v0, d);
        float a1 = __shfl_down_sync(0xffffffffu, v1, d);
        if (lane + d < 32 && go == g) { c += co; v0 += a0; v1 += a1; }
    }

    int  gprev = __shfl_up_sync(0xffffffffu, g, 1);
    bool head  = (lane == 0) || (gprev != g);
    if (head && g >= 0 && g < MAXG)
        red_add_v4_relaxed(&g_state[g], make_float4(c, v0, v1, 0.f));
}

extern "C" void kernel_launch(void* const* d_in, const int* in_sizes, int n_in,
                              void* d_out, int out_size)
{
    // order: node_features, batch, graph_embedding, W1, b1, W2, b2
    const float* nf    = (const float*)d_in[0];
    const int*   batch = (const int*)d_in[1];
    const float* W1    = (const float*)d_in[3];
    const float* b1    = (const float*)d_in[4];
    const float* W2    = (const float*)d_in[5];
    const float* b2    = (const float*)d_in[6];
    float*       out   = (float*)d_out;

    int N = in_sizes[1];
    int G = in_sizes[2] / F_DIM;
    if (G <= 0 || G > MAXG) G = out_size;

    int rb = (N + 255) / 256;
    fused_kernel<<<WAITER_BLOCKS + rb, 256>>>(nf, batch, W1, b1, W2, b2, out, N, G);
}